// round 2
// baseline (speedup 1.0000x reference)
#include <cuda_runtime.h>

#define Bb 4
#define Qq 512
#define Kk 1024
#define QSd 256
#define KSd 256
#define VDd 256
#define Hh 128
#define NEGV -1e9f

#define QT 16            // q rows per block
#define KC 64            // k chunk
#define KS_STRIDE 129    // padded k-tile stride (2-way max conflicts)

// Scratch (no allocations allowed): projected q/k.
__device__ __align__(16) float g_qp[Bb * Qq * Hh];   // 1 MB
__device__ __align__(16) float g_kp[Bb * Kk * Hh];   // 2 MB

__device__ __forceinline__ float tanh_fast(float x) {
    float y;
    asm("tanh.approx.f32 %0, %1;" : "=f"(y) : "f"(x));
    return y;
}

// ---------------------------------------------------------------------------
// Projection: C[M,128] = A[M,256] @ W[256,128]. which=0 -> g_qp, 1 -> g_kp.
// ---------------------------------------------------------------------------
__global__ void proj_kernel(const float* __restrict__ A,
                            const float* __restrict__ W,
                            int which) {
    __shared__ float a_s[16][256];
    __shared__ float w_s[32][128];
    float* C = which ? g_kp : g_qp;

    const int tid  = threadIdx.x;
    const int row0 = blockIdx.x * 16;

    #pragma unroll
    for (int i = 0; i < 16; i++)
        a_s[i][tid] = A[(row0 + i) * 256 + tid];

    const int col = tid & 127;
    const int rg  = tid >> 7;
    float acc[8];
    #pragma unroll
    for (int i = 0; i < 8; i++) acc[i] = 0.f;

    for (int dc = 0; dc < 256; dc += 32) {
        __syncthreads();
        #pragma unroll
        for (int i = 0; i < 16; i++) {
            int idx = i * 256 + tid;
            w_s[idx >> 7][idx & 127] = W[(dc + (idx >> 7)) * 128 + (idx & 127)];
        }
        __syncthreads();
        #pragma unroll 8
        for (int d = 0; d < 32; d++) {
            float wv = w_s[d][col];
            #pragma unroll
            for (int i = 0; i < 8; i++)
                acc[i] += a_s[rg * 8 + i][dc + d] * wv;
        }
    }
    #pragma unroll
    for (int i = 0; i < 8; i++)
        C[(row0 + rg * 8 + i) * 128 + col] = acc[i];
}

// ---------------------------------------------------------------------------
// Fused: scores (tanh additive) + mask + online softmax + attn@V.
// Grid (Q/QT, B) = (32, 4), 256 threads.
// Score threads: (ty,tx) = (tid>>5, tid&31), 2x2 micro-tile over 16q x 64k.
//   -> warp ty owns score rows 2ty, 2ty+1 entirely (shuffle row-reductions).
// AV threads:    (qi,vg) = (tid>>4, tid&15): 1 q row x 16 v cols (4 float4).
// Chunks with k0 >= valid_len are skipped (masked probs are exactly 0).
// ---------------------------------------------------------------------------
__global__ void fused_attn(const float* __restrict__ values,
                           const int* __restrict__ valid_lens,
                           const float* __restrict__ w_v,
                           float* __restrict__ out) {
    extern __shared__ float sm[];
    float* vs   = sm;                       // KC * 256        (64 KB)
    float* qs   = vs + KC * VDd;            // QT * 128        (8 KB)
    float* ks   = qs + QT * Hh;             // KC * 129        (33 KB)
    float* p_s  = ks + KC * KS_STRIDE;      // QT * KC         (4 KB)
    float* ws   = p_s + QT * KC;            // 128
    float* al_s = ws + Hh;                  // QT
    float* iv_s = al_s + QT;                // QT

    const int b   = blockIdx.y;
    const int q0  = blockIdx.x * QT;
    const int tid = threadIdx.x;
    const int vl  = valid_lens[b];

    // Load q tile (16 x 128) and w_v.
    const float4* qp4 = (const float4*)(g_qp + (b * Qq + q0) * Hh);
    #pragma unroll
    for (int i = 0; i < 2; i++)
        ((float4*)qs)[i * 256 + tid] = qp4[i * 256 + tid];
    if (tid < Hh) ws[tid] = w_v[tid];

    const int ty = tid >> 5, tx = tid & 31;   // scores mapping
    const int qi = tid >> 4, vg = tid & 15;   // AV mapping

    float m0 = -3.0e38f, m1 = -3.0e38f, l0 = 0.f, l1 = 0.f;
    float4 acc0 = make_float4(0.f, 0.f, 0.f, 0.f);
    float4 acc1 = acc0, acc2 = acc0, acc3 = acc0;

    const int nchunk = (vl + KC - 1) / KC;
    for (int c = 0; c < nchunk; c++) {
        const int kc = c * KC;
        __syncthreads();   // previous AV reads done before overwriting tiles

        // k tile: 64 rows x 128 h -> ks[r*129 + h]. Coalesced float4 loads.
        const float4* kp4 = (const float4*)(g_kp + (b * Kk + kc) * Hh);
        #pragma unroll
        for (int i = 0; i < 8; i++) {
            int e  = i * 256 + tid;       // float4 index; r = e>>5, c4 = e&31
            int r  = e >> 5, c4 = e & 31;
            float4 kv = kp4[e];
            float* dst = ks + r * KS_STRIDE + c4 * 4;
            dst[0] = kv.x; dst[1] = kv.y; dst[2] = kv.z; dst[3] = kv.w;
        }
        // values tile: 64 x 256 floats = 4096 float4.
        const float4* v4 = (const float4*)(values + ((size_t)b * Kk + kc) * VDd);
        #pragma unroll
        for (int i = 0; i < 16; i++)
            ((float4*)vs)[i * 256 + tid] = v4[i * 256 + tid];
        __syncthreads();

        // ---- scores 2x2 micro-tile ----
        float s00 = 0.f, s01 = 0.f, s10 = 0.f, s11 = 0.f;
        const float* qa = qs + (2 * ty) * Hh;
        const float* qb = qa + Hh;
        const float* ka = ks + (2 * tx) * KS_STRIDE;
        const float* kb = ka + KS_STRIDE;
        #pragma unroll 8
        for (int h = 0; h < Hh; h++) {
            float w   = ws[h];
            float qv0 = qa[h], qv1 = qb[h];
            float kv0 = ka[h], kv1 = kb[h];
            s00 += w * tanh_fast(qv0 + kv0);
            s01 += w * tanh_fast(qv0 + kv1);
            s10 += w * tanh_fast(qv1 + kv0);
            s11 += w * tanh_fast(qv1 + kv1);
        }
        const int ke = kc + 2 * tx;
        if (ke     >= vl) { s00 = NEGV; s10 = NEGV; }
        if (ke + 1 >= vl) { s01 = NEGV; s11 = NEGV; }

        // ---- online softmax (per-warp rows) ----
        float cm0 = fmaxf(s00, s01), cm1 = fmaxf(s10, s11);
        #pragma unroll
        for (int o = 16; o; o >>= 1) {
            cm0 = fmaxf(cm0, __shfl_xor_sync(~0u, cm0, o));
            cm1 = fmaxf(cm1, __shfl_xor_sync(~0u, cm1, o));
        }
        float mn0 = fmaxf(m0, cm0), mn1 = fmaxf(m1, cm1);
        float a0  = __expf(m0 - mn0), a1 = __expf(m1 - mn1);
        float p00 = __expf(s00 - mn0), p01 = __expf(s01 - mn0);
        float p10 = __expf(s10 - mn1), p11 = __expf(s11 - mn1);
        float rs0 = p00 + p01, rs1 = p10 + p11;
        #pragma unroll
        for (int o = 16; o; o >>= 1) {
            rs0 += __shfl_xor_sync(~0u, rs0, o);
            rs1 += __shfl_xor_sync(~0u, rs1, o);
        }
        l0 = l0 * a0 + rs0;
        l1 = l1 * a1 + rs1;
        m0 = mn0; m1 = mn1;

        *(float2*)&p_s[(2 * ty)     * KC + 2 * tx] = make_float2(p00, p01);
        *(float2*)&p_s[(2 * ty + 1) * KC + 2 * tx] = make_float2(p10, p11);
        if (tx == 0) { al_s[2 * ty] = a0; al_s[2 * ty + 1] = a1; }
        __syncthreads();

        // ---- AV accumulate ----
        float av = al_s[qi];
        acc0.x *= av; acc0.y *= av; acc0.z *= av; acc0.w *= av;
        acc1.x *= av; acc1.y *= av; acc1.z *= av; acc1.w *= av;
        acc2.x *= av; acc2.y *= av; acc2.z *= av; acc2.w *= av;
        acc3.x *= av; acc3.y *= av; acc3.z *= av; acc3.w *= av;

        const float*  pr = p_s + qi * KC;
        const float4* vr = (const float4*)vs + vg * 4;
        const int klim = (vl - kc < KC) ? (vl - kc) : KC;
        #pragma unroll 4
        for (int k = 0; k < klim; k++) {
            float a = pr[k];
            const float4* vrow = vr + k * (VDd / 4);
            float4 v0 = vrow[0], v1 = vrow[1], v2 = vrow[2], v3 = vrow[3];
            acc0.x += a * v0.x; acc0.y += a * v0.y; acc0.z += a * v0.z; acc0.w += a * v0.w;
            acc1.x += a * v1.x; acc1.y += a * v1.y; acc1.z += a * v1.z; acc1.w += a * v1.w;
            acc2.x += a * v2.x; acc2.y += a * v2.y; acc2.z += a * v2.z; acc2.w += a * v2.w;
            acc3.x += a * v3.x; acc3.y += a * v3.y; acc3.z += a * v3.z; acc3.w += a * v3.w;
        }
    }

    // ---- epilogue: normalize and store ----
    if (tx == 0) {
        iv_s[2 * ty]     = __frcp_rn(l0);
        iv_s[2 * ty + 1] = __frcp_rn(l1);
    }
    __syncthreads();
    float inv = iv_s[qi];
    acc0.x *= inv; acc0.y *= inv; acc0.z *= inv; acc0.w *= inv;
    acc1.x *= inv; acc1.y *= inv; acc1.z *= inv; acc1.w *= inv;
    acc2.x *= inv; acc2.y *= inv; acc2.z *= inv; acc2.w *= inv;
    acc3.x *= inv; acc3.y *= inv; acc3.z *= inv; acc3.w *= inv;

    float4* o = (float4*)(out + ((size_t)(b * Qq + q0 + qi)) * VDd) + vg * 4;
    o[0] = acc0; o[1] = acc1; o[2] = acc2; o[3] = acc3;
}

// ---------------------------------------------------------------------------
extern "C" void kernel_launch(void* const* d_in, const int* in_sizes, int n_in,
                              void* d_out, int out_size) {
    const float* queries    = (const float*)d_in[0];
    const float* keys       = (const float*)d_in[1];
    const float* values     = (const float*)d_in[2];
    const int*   valid_lens = (const int*)  d_in[3];
    const float* W_q        = (const float*)d_in[4];
    const float* W_k        = (const float*)d_in[5];
    const float* w_v        = (const float*)d_in[6];
    float* out = (float*)d_out;

    const int smem_bytes = (KC * VDd + QT * Hh + KC * KS_STRIDE +
                            QT * KC + Hh + 2 * QT) * (int)sizeof(float);
    cudaFuncSetAttribute(fused_attn, cudaFuncAttributeMaxDynamicSharedMemorySize,
                         smem_bytes);

    proj_kernel<<<(Bb * Qq) / 16, 256>>>(queries, W_q, 0);
    proj_kernel<<<(Bb * Kk) / 16, 256>>>(keys,    W_k, 1);

    fused_attn<<<dim3(Qq / QT, Bb), 256, smem_bytes>>>(values, valid_lens,
                                                       w_v, out);
}

// round 3
// speedup vs baseline: 1.9204x; 1.9204x over previous
#include <cuda_runtime.h>

#define Bb 4
#define Qq 512
#define Kk 1024
#define VDd 256
#define Hh 128

#define QS_STRIDE 132   // q smem stride (16B-aligned float4, conflict-free)
#define KS_STRIDE 129   // k smem stride (2-way max conflicts)

// Scratch (no allocations allowed).
__device__ __align__(16) float g_qp[Bb * Qq * Hh];   // 1 MB
__device__ __align__(16) float g_kp[Bb * Kk * Hh];   // 2 MB
__device__ __align__(16) float g_sc[Bb * Qq * Kk];   // 8 MB

__device__ __forceinline__ float tanh_fast(float x) {
    float y;
    asm("tanh.approx.f32 %0, %1;" : "=f"(y) : "f"(x));
    return y;
}

// ---------------------------------------------------------------------------
// Combined projection: g_qp = queries@W_q, g_kp = keys@W_k.
// Grid 384 blocks (128 q-tiles + 256 k-tiles), 256 threads, 16 rows/block.
// ---------------------------------------------------------------------------
__global__ void proj_kernel(const float* __restrict__ queries,
                            const float* __restrict__ W_q,
                            const float* __restrict__ keys,
                            const float* __restrict__ W_k) {
    __shared__ float a_s[16][256];
    __shared__ float w_s[32][128];

    const int bx = blockIdx.x;
    const float* A; const float* W; float* C; int row0;
    if (bx < (Bb * Qq) / 16) { A = queries; W = W_q; C = g_qp; row0 = bx * 16; }
    else { A = keys; W = W_k; C = g_kp; row0 = (bx - (Bb * Qq) / 16) * 16; }

    const int tid = threadIdx.x;
    #pragma unroll
    for (int i = 0; i < 16; i++)
        a_s[i][tid] = A[(row0 + i) * 256 + tid];

    const int col = tid & 127;
    const int rg  = tid >> 7;
    float acc[8];
    #pragma unroll
    for (int i = 0; i < 8; i++) acc[i] = 0.f;

    for (int dc = 0; dc < 256; dc += 32) {
        __syncthreads();
        #pragma unroll
        for (int i = 0; i < 16; i++) {
            int idx = i * 256 + tid;
            w_s[idx >> 7][idx & 127] = W[(dc + (idx >> 7)) * 128 + (idx & 127)];
        }
        __syncthreads();
        #pragma unroll 8
        for (int d = 0; d < 32; d++) {
            float wv = w_s[d][col];
            #pragma unroll
            for (int i = 0; i < 8; i++)
                acc[i] += a_s[rg * 8 + i][dc + d] * wv;
        }
    }
    #pragma unroll
    for (int i = 0; i < 8; i++)
        C[(row0 + rg * 8 + i) * 128 + col] = acc[i];
}

// ---------------------------------------------------------------------------
// Scores: sc[b][q][k] = sum_h w[h]*tanh(qp+kp). 64q x 64k tile, 256 threads,
// 4x4 micro-tile. Tiles fully beyond valid_len exit immediately; no mask
// writes needed (softmax/AV only touch k < valid_len).
// ---------------------------------------------------------------------------
__global__ void scores_kernel(const float* __restrict__ w_v,
                              const int* __restrict__ valid_lens) {
    const int b  = blockIdx.z;
    const int k0 = blockIdx.x * 64;
    if (k0 >= valid_lens[b]) return;          // masked tile: nothing downstream reads it
    const int q0 = blockIdx.y * 64;

    extern __shared__ float sm[];
    float* qs = sm;                           // 64 * 132
    float* ks = qs + 64 * QS_STRIDE;          // 64 * 129
    float* ws = ks + 64 * KS_STRIDE;          // 128

    const int tid = threadIdx.x;

    // q tile: 64 x 128, float4 coalesced into stride-132 rows.
    const float4* qp4 = (const float4*)(g_qp + (b * Qq + q0) * Hh);
    #pragma unroll
    for (int i = 0; i < 8; i++) {
        int e = i * 256 + tid;                // float4 idx: row=e>>5, c4=e&31
        ((float4*)(qs + (e >> 5) * QS_STRIDE))[e & 31] = qp4[e];
    }
    // k tile: 64 x 128 into stride-129 rows (scalar stores; odd stride).
    const float4* kp4 = (const float4*)(g_kp + (b * Kk + k0) * Hh);
    #pragma unroll
    for (int i = 0; i < 8; i++) {
        int e = i * 256 + tid;
        float4 kv = kp4[e];
        float* dst = ks + (e >> 5) * KS_STRIDE + (e & 31) * 4;
        dst[0] = kv.x; dst[1] = kv.y; dst[2] = kv.z; dst[3] = kv.w;
    }
    if (tid < Hh) ws[tid] = w_v[tid];
    __syncthreads();

    const int tx = tid & 15;                  // k group (4 cols)
    const int ty = tid >> 4;                  // q group (4 rows)
    const float* qb = qs + (4 * ty) * QS_STRIDE;
    const float* kb = ks + (4 * tx) * KS_STRIDE;

    float acc[4][4];
    #pragma unroll
    for (int i = 0; i < 4; i++)
        #pragma unroll
        for (int j = 0; j < 4; j++) acc[i][j] = 0.f;

    #pragma unroll 4
    for (int h = 0; h < Hh; h++) {
        float w = ws[h];
        float qv0 = qb[0 * QS_STRIDE + h], qv1 = qb[1 * QS_STRIDE + h];
        float qv2 = qb[2 * QS_STRIDE + h], qv3 = qb[3 * QS_STRIDE + h];
        float kv0 = kb[0 * KS_STRIDE + h], kv1 = kb[1 * KS_STRIDE + h];
        float kv2 = kb[2 * KS_STRIDE + h], kv3 = kb[3 * KS_STRIDE + h];
        acc[0][0] += w * tanh_fast(qv0 + kv0);
        acc[0][1] += w * tanh_fast(qv0 + kv1);
        acc[0][2] += w * tanh_fast(qv0 + kv2);
        acc[0][3] += w * tanh_fast(qv0 + kv3);
        acc[1][0] += w * tanh_fast(qv1 + kv0);
        acc[1][1] += w * tanh_fast(qv1 + kv1);
        acc[1][2] += w * tanh_fast(qv1 + kv2);
        acc[1][3] += w * tanh_fast(qv1 + kv3);
        acc[2][0] += w * tanh_fast(qv2 + kv0);
        acc[2][1] += w * tanh_fast(qv2 + kv1);
        acc[2][2] += w * tanh_fast(qv2 + kv2);
        acc[2][3] += w * tanh_fast(qv2 + kv3);
        acc[3][0] += w * tanh_fast(qv3 + kv0);
        acc[3][1] += w * tanh_fast(qv3 + kv1);
        acc[3][2] += w * tanh_fast(qv3 + kv2);
        acc[3][3] += w * tanh_fast(qv3 + kv3);
    }

    #pragma unroll
    for (int i = 0; i < 4; i++) {
        float4 r = make_float4(acc[i][0], acc[i][1], acc[i][2], acc[i][3]);
        *(float4*)&g_sc[(size_t)(b * Qq + q0 + 4 * ty + i) * Kk + k0 + 4 * tx] = r;
    }
}

// ---------------------------------------------------------------------------
// Softmax over k < valid_len; writes zeros beyond (AV-safe), in place on g_sc.
// ---------------------------------------------------------------------------
__global__ void softmax_kernel(const int* __restrict__ valid_lens) {
    const int row = blockIdx.x;               // b*Qq + q
    const int b   = row >> 9;                 // Qq = 512
    const int vl  = valid_lens[b];
    const int tid = threadIdx.x;
    const float NINF = __int_as_float(0xff800000);

    float4* p = (float4*)&g_sc[(size_t)row * Kk];
    float4 v = p[tid];
    const int k = 4 * tid;
    float e0 = (k     < vl) ? v.x : NINF;
    float e1 = (k + 1 < vl) ? v.y : NINF;
    float e2 = (k + 2 < vl) ? v.z : NINF;
    float e3 = (k + 3 < vl) ? v.w : NINF;

    __shared__ float redm[8];
    __shared__ float reds[8];
    const int wid = tid >> 5, lid = tid & 31;

    float m = fmaxf(fmaxf(e0, e1), fmaxf(e2, e3));
    #pragma unroll
    for (int o = 16; o; o >>= 1) m = fmaxf(m, __shfl_xor_sync(~0u, m, o));
    if (lid == 0) redm[wid] = m;
    __syncthreads();
    m = redm[0];
    #pragma unroll
    for (int i = 1; i < 8; i++) m = fmaxf(m, redm[i]);

    float p0 = (k     < vl) ? __expf(e0 - m) : 0.f;
    float p1 = (k + 1 < vl) ? __expf(e1 - m) : 0.f;
    float p2 = (k + 2 < vl) ? __expf(e2 - m) : 0.f;
    float p3 = (k + 3 < vl) ? __expf(e3 - m) : 0.f;

    float s = p0 + p1 + p2 + p3;
    #pragma unroll
    for (int o = 16; o; o >>= 1) s += __shfl_xor_sync(~0u, s, o);
    if (lid == 0) reds[wid] = s;
    __syncthreads();
    s = reds[0];
    #pragma unroll
    for (int i = 1; i < 8; i++) s += reds[i];

    float inv = __frcp_rn(s);
    p[tid] = make_float4(p0 * inv, p1 * inv, p2 * inv, p3 * inv);
}

// ---------------------------------------------------------------------------
// AV: out = attn @ values, K-loop bounded by valid_len.
// Grid (VD/64, Q/16, B) = 512 blocks, 256 threads. 16q x 64v per block.
// ---------------------------------------------------------------------------
__global__ void av_kernel(const float* __restrict__ values,
                          const int* __restrict__ valid_lens,
                          float* __restrict__ out) {
    __shared__ __align__(16) float at_s[16 * 32];
    __shared__ __align__(16) float vs_s[32 * 64];

    const int b  = blockIdx.z;
    const int q0 = blockIdx.y * 16;
    const int v0 = blockIdx.x * 64;
    const int tid = threadIdx.x;
    const int vt = tid & 15;
    const int qi = tid >> 4;
    const int vl = valid_lens[b];

    const float* attn = g_sc + (size_t)(b * Qq + q0) * Kk;
    const float* vals = values + (size_t)b * Kk * VDd + v0;

    float4 acc = make_float4(0.f, 0.f, 0.f, 0.f);

    for (int kc = 0; kc < vl; kc += 32) {
        __syncthreads();
        #pragma unroll
        for (int i = 0; i < 2; i++) {
            int e = i * 256 + tid;
            at_s[e] = attn[(e >> 5) * Kk + kc + (e & 31)];
        }
        #pragma unroll
        for (int i = 0; i < 2; i++) {
            int e = i * 256 + tid;
            ((float4*)vs_s)[e] = ((const float4*)(vals + (size_t)(kc + (e >> 4)) * VDd))[e & 15];
        }
        __syncthreads();
        const int klim = (vl - kc < 32) ? (vl - kc) : 32;
        #pragma unroll 8
        for (int kk = 0; kk < klim; kk++) {
            float a = at_s[qi * 32 + kk];
            float4 vv = ((float4*)vs_s)[kk * 16 + vt];
            acc.x += a * vv.x;
            acc.y += a * vv.y;
            acc.z += a * vv.z;
            acc.w += a * vv.w;
        }
    }

    float4* o = (float4*)(out + (size_t)(b * Qq + q0 + qi) * VDd + v0);
    o[vt] = acc;
}

// ---------------------------------------------------------------------------
extern "C" void kernel_launch(void* const* d_in, const int* in_sizes, int n_in,
                              void* d_out, int out_size) {
    const float* queries    = (const float*)d_in[0];
    const float* keys       = (const float*)d_in[1];
    const float* values     = (const float*)d_in[2];
    const int*   valid_lens = (const int*)  d_in[3];
    const float* W_q        = (const float*)d_in[4];
    const float* W_k        = (const float*)d_in[5];
    const float* w_v        = (const float*)d_in[6];
    float* out = (float*)d_out;

    proj_kernel<<<(Bb * Qq) / 16 + (Bb * Kk) / 16, 256>>>(queries, W_q, keys, W_k);

    const int sc_smem = (64 * QS_STRIDE + 64 * KS_STRIDE + Hh) * (int)sizeof(float);
    cudaFuncSetAttribute(scores_kernel, cudaFuncAttributeMaxDynamicSharedMemorySize,
                         sc_smem);
    scores_kernel<<<dim3(Kk / 64, Qq / 64, Bb), 256, sc_smem>>>(w_v, valid_lens);

    softmax_kernel<<<Bb * Qq, 256>>>(valid_lens);

    av_kernel<<<dim3(VDd / 64, Qq / 16, Bb), 256>>>(values, valid_lens, out);
}

// round 4
// speedup vs baseline: 1.9951x; 1.0389x over previous
#include <cuda_runtime.h>

#define Bb 4
#define Qq 512
#define Kk 1024
#define VDd 256
#define Hh 128

#define QS_STRIDE 132   // scores q smem stride
#define KS_STRIDE 129   // scores k smem stride
#define AT_STRIDE 68    // av attn smem stride (16B aligned, conflict-free bcast)

// Scratch (no allocations allowed).
__device__ __align__(16) float g_qp[Bb * Qq * Hh];   // 1 MB
__device__ __align__(16) float g_kp[Bb * Kk * Hh];   // 2 MB
__device__ __align__(16) float g_sc[Bb * Qq * Kk];   // 8 MB

__device__ __forceinline__ float tanh_fast(float x) {
    float y;
    asm("tanh.approx.f32 %0, %1;" : "=f"(y) : "f"(x));
    return y;
}

// ---------------------------------------------------------------------------
// Combined projection: g_qp = queries@W_q, g_kp = keys@W_k. 384 blocks.
// ---------------------------------------------------------------------------
__global__ void proj_kernel(const float* __restrict__ queries,
                            const float* __restrict__ W_q,
                            const float* __restrict__ keys,
                            const float* __restrict__ W_k) {
    __shared__ float a_s[16][256];
    __shared__ float w_s[32][128];

    const int bx = blockIdx.x;
    const float* A; const float* W; float* C; int row0;
    if (bx < (Bb * Qq) / 16) { A = queries; W = W_q; C = g_qp; row0 = bx * 16; }
    else { A = keys; W = W_k; C = g_kp; row0 = (bx - (Bb * Qq) / 16) * 16; }

    const int tid = threadIdx.x;
    #pragma unroll
    for (int i = 0; i < 16; i++)
        a_s[i][tid] = A[(row0 + i) * 256 + tid];

    const int col = tid & 127;
    const int rg  = tid >> 7;
    float acc[8];
    #pragma unroll
    for (int i = 0; i < 8; i++) acc[i] = 0.f;

    for (int dc = 0; dc < 256; dc += 32) {
        __syncthreads();
        #pragma unroll
        for (int i = 0; i < 16; i++) {
            int idx = i * 256 + tid;
            w_s[idx >> 7][idx & 127] = W[(dc + (idx >> 7)) * 128 + (idx & 127)];
        }
        __syncthreads();
        #pragma unroll 8
        for (int d = 0; d < 32; d++) {
            float wv = w_s[d][col];
            #pragma unroll
            for (int i = 0; i < 8; i++)
                acc[i] += a_s[rg * 8 + i][dc + d] * wv;
        }
    }
    #pragma unroll
    for (int i = 0; i < 8; i++)
        C[(row0 + rg * 8 + i) * 128 + col] = acc[i];
}

// ---------------------------------------------------------------------------
// Scores: 64q x 64k tile, 4x4 micro-tile; masked tiles exit immediately.
// ---------------------------------------------------------------------------
__global__ void scores_kernel(const float* __restrict__ w_v,
                              const int* __restrict__ valid_lens) {
    const int b  = blockIdx.z;
    const int k0 = blockIdx.x * 64;
    if (k0 >= valid_lens[b]) return;
    const int q0 = blockIdx.y * 64;

    extern __shared__ float sm[];
    float* qs = sm;                           // 64 * 132
    float* ks = qs + 64 * QS_STRIDE;          // 64 * 129
    float* ws = ks + 64 * KS_STRIDE;          // 128

    const int tid = threadIdx.x;

    const float4* qp4 = (const float4*)(g_qp + (b * Qq + q0) * Hh);
    #pragma unroll
    for (int i = 0; i < 8; i++) {
        int e = i * 256 + tid;
        ((float4*)(qs + (e >> 5) * QS_STRIDE))[e & 31] = qp4[e];
    }
    const float4* kp4 = (const float4*)(g_kp + (b * Kk + k0) * Hh);
    #pragma unroll
    for (int i = 0; i < 8; i++) {
        int e = i * 256 + tid;
        float4 kv = kp4[e];
        float* dst = ks + (e >> 5) * KS_STRIDE + (e & 31) * 4;
        dst[0] = kv.x; dst[1] = kv.y; dst[2] = kv.z; dst[3] = kv.w;
    }
    if (tid < Hh) ws[tid] = w_v[tid];
    __syncthreads();

    const int tx = tid & 15;
    const int ty = tid >> 4;
    const float* qb = qs + (4 * ty) * QS_STRIDE;
    const float* kb = ks + (4 * tx) * KS_STRIDE;

    float acc[4][4];
    #pragma unroll
    for (int i = 0; i < 4; i++)
        #pragma unroll
        for (int j = 0; j < 4; j++) acc[i][j] = 0.f;

    #pragma unroll 4
    for (int h = 0; h < Hh; h++) {
        float w = ws[h];
        float qv0 = qb[0 * QS_STRIDE + h], qv1 = qb[1 * QS_STRIDE + h];
        float qv2 = qb[2 * QS_STRIDE + h], qv3 = qb[3 * QS_STRIDE + h];
        float kv0 = kb[0 * KS_STRIDE + h], kv1 = kb[1 * KS_STRIDE + h];
        float kv2 = kb[2 * KS_STRIDE + h], kv3 = kb[3 * KS_STRIDE + h];
        acc[0][0] += w * tanh_fast(qv0 + kv0);
        acc[0][1] += w * tanh_fast(qv0 + kv1);
        acc[0][2] += w * tanh_fast(qv0 + kv2);
        acc[0][3] += w * tanh_fast(qv0 + kv3);
        acc[1][0] += w * tanh_fast(qv1 + kv0);
        acc[1][1] += w * tanh_fast(qv1 + kv1);
        acc[1][2] += w * tanh_fast(qv1 + kv2);
        acc[1][3] += w * tanh_fast(qv1 + kv3);
        acc[2][0] += w * tanh_fast(qv2 + kv0);
        acc[2][1] += w * tanh_fast(qv2 + kv1);
        acc[2][2] += w * tanh_fast(qv2 + kv2);
        acc[2][3] += w * tanh_fast(qv2 + kv3);
        acc[3][0] += w * tanh_fast(qv3 + kv0);
        acc[3][1] += w * tanh_fast(qv3 + kv1);
        acc[3][2] += w * tanh_fast(qv3 + kv2);
        acc[3][3] += w * tanh_fast(qv3 + kv3);
    }

    #pragma unroll
    for (int i = 0; i < 4; i++) {
        float4 r = make_float4(acc[i][0], acc[i][1], acc[i][2], acc[i][3]);
        *(float4*)&g_sc[(size_t)(b * Qq + q0 + 4 * ty + i) * Kk + k0 + 4 * tx] = r;
    }
}

// ---------------------------------------------------------------------------
// Softmax over k < valid_len; writes EXACT zeros beyond (AV relies on this).
// ---------------------------------------------------------------------------
__global__ void softmax_kernel(const int* __restrict__ valid_lens) {
    const int row = blockIdx.x;
    const int b   = row >> 9;
    const int vl  = valid_lens[b];
    const int tid = threadIdx.x;
    const float NINF = __int_as_float(0xff800000);

    float4* p = (float4*)&g_sc[(size_t)row * Kk];
    float4 v = p[tid];
    const int k = 4 * tid;
    float e0 = (k     < vl) ? v.x : NINF;
    float e1 = (k + 1 < vl) ? v.y : NINF;
    float e2 = (k + 2 < vl) ? v.z : NINF;
    float e3 = (k + 3 < vl) ? v.w : NINF;

    __shared__ float redm[8];
    __shared__ float reds[8];
    const int wid = tid >> 5, lid = tid & 31;

    float m = fmaxf(fmaxf(e0, e1), fmaxf(e2, e3));
    #pragma unroll
    for (int o = 16; o; o >>= 1) m = fmaxf(m, __shfl_xor_sync(~0u, m, o));
    if (lid == 0) redm[wid] = m;
    __syncthreads();
    m = redm[0];
    #pragma unroll
    for (int i = 1; i < 8; i++) m = fmaxf(m, redm[i]);

    float p0 = (k     < vl) ? __expf(e0 - m) : 0.f;
    float p1 = (k + 1 < vl) ? __expf(e1 - m) : 0.f;
    float p2 = (k + 2 < vl) ? __expf(e2 - m) : 0.f;
    float p3 = (k + 3 < vl) ? __expf(e3 - m) : 0.f;

    float s = p0 + p1 + p2 + p3;
    #pragma unroll
    for (int o = 16; o; o >>= 1) s += __shfl_xor_sync(~0u, s, o);
    if (lid == 0) reds[wid] = s;
    __syncthreads();
    s = reds[0];
    #pragma unroll
    for (int i = 1; i < 8; i++) s += reds[i];

    float inv = __frcp_rn(s);
    p[tid] = make_float4(p0 * inv, p1 * inv, p2 * inv, p3 * inv);
}

// ---------------------------------------------------------------------------
// AV: out = attn @ values. Tile 64q x 64v, k-chunk 64, 512 threads.
// Thread: 2 q rows x 4 v cols. Register double-buffered gmem loads.
// Grid (VD/64, Q/64, B) = (4, 8, 4) = 128 blocks.
// ---------------------------------------------------------------------------
__global__ void __launch_bounds__(512)
av_kernel(const float* __restrict__ values,
          const int* __restrict__ valid_lens,
          float* __restrict__ out) {
    __shared__ __align__(16) float at_s[64 * AT_STRIDE];   // ~17 KB
    __shared__ __align__(16) float vs_s[64 * 64];          // 16 KB

    const int b   = blockIdx.z;
    const int q0  = blockIdx.y * 64;
    const int v0  = blockIdx.x * 64;
    const int tid = threadIdx.x;
    const int tx  = tid & 15;         // 4 v cols: 4*tx
    const int ty  = tid >> 4;         // 2 q rows: 2*ty
    const int vl  = valid_lens[b];

    const float* attn = g_sc + (size_t)(b * Qq + q0) * Kk;
    const float* vals = values + (size_t)b * Kk * VDd + v0;

    // Load indices (1024 float4 per tile, 2 per thread).
    const int ar0 = tid >> 4, ac0 = tid & 15;          // attn: e = tid
    const int ar1 = (tid + 512) >> 4, ac1 = ac0;       // e = tid + 512
    const int vr0 = ar0, vc0 = ac0;                    // v: same shape
    const int vr1 = ar1, vc1 = ac1;

    float4 pa0, pa1, pv0, pv1;
    // Prefetch chunk 0.
    pa0 = ((const float4*)(attn + (size_t)ar0 * Kk))[ac0];
    pa1 = ((const float4*)(attn + (size_t)ar1 * Kk))[ac1];
    pv0 = ((const float4*)(vals + (size_t)vr0 * VDd))[vc0];
    pv1 = ((const float4*)(vals + (size_t)vr1 * VDd))[vc1];

    float4 acc0 = make_float4(0.f, 0.f, 0.f, 0.f);
    float4 acc1 = acc0;

    const int nchunk = (vl + 63) >> 6;
    for (int c = 0; c < nchunk; c++) {
        // Commit prefetched chunk to smem.
        ((float4*)(at_s + ar0 * AT_STRIDE))[ac0] = pa0;
        ((float4*)(at_s + ar1 * AT_STRIDE))[ac1] = pa1;
        ((float4*)(vs_s + vr0 * 64))[vc0] = pv0;
        ((float4*)(vs_s + vr1 * 64))[vc1] = pv1;
        __syncthreads();

        // Prefetch next chunk from gmem (overlaps with compute below).
        if (c + 1 < nchunk) {
            const float* an = attn + (c + 1) * 64;
            const float* vn = vals + (size_t)(c + 1) * 64 * VDd;
            pa0 = ((const float4*)(an + (size_t)ar0 * Kk))[ac0];
            pa1 = ((const float4*)(an + (size_t)ar1 * Kk))[ac1];
            pv0 = ((const float4*)(vn + (size_t)vr0 * VDd))[vc0];
            pv1 = ((const float4*)(vn + (size_t)vr1 * VDd))[vc1];
        }

        // Compute: 64 k-steps, 2q x 4v per thread.
        const float* a0 = at_s + (2 * ty)     * AT_STRIDE;
        const float* a1 = at_s + (2 * ty + 1) * AT_STRIDE;
        const float4* vrow = (const float4*)vs_s + tx;
        #pragma unroll 8
        for (int k = 0; k < 64; k++) {
            float w0 = a0[k], w1 = a1[k];
            float4 vv = vrow[k * 16];
            acc0.x += w0 * vv.x; acc0.y += w0 * vv.y;
            acc0.z += w0 * vv.z; acc0.w += w0 * vv.w;
            acc1.x += w1 * vv.x; acc1.y += w1 * vv.y;
            acc1.z += w1 * vv.z; acc1.w += w1 * vv.w;
        }
        __syncthreads();
    }

    float4* o0 = (float4*)(out + (size_t)(b * Qq + q0 + 2 * ty) * VDd + v0);
    float4* o1 = (float4*)(out + (size_t)(b * Qq + q0 + 2 * ty + 1) * VDd + v0);
    o0[tx] = acc0;
    o1[tx] = acc1;
}

// ---------------------------------------------------------------------------
extern "C" void kernel_launch(void* const* d_in, const int* in_sizes, int n_in,
                              void* d_out, int out_size) {
    const float* queries    = (const float*)d_in[0];
    const float* keys       = (const float*)d_in[1];
    const float* values     = (const float*)d_in[2];
    const int*   valid_lens = (const int*)  d_in[3];
    const float* W_q        = (const float*)d_in[4];
    const float* W_k        = (const float*)d_in[5];
    const float* w_v        = (const float*)d_in[6];
    float* out = (float*)d_out;

    proj_kernel<<<(Bb * Qq) / 16 + (Bb * Kk) / 16, 256>>>(queries, W_q, keys, W_k);

    const int sc_smem = (64 * QS_STRIDE + 64 * KS_STRIDE + Hh) * (int)sizeof(float);
    cudaFuncSetAttribute(scores_kernel, cudaFuncAttributeMaxDynamicSharedMemorySize,
                         sc_smem);
    scores_kernel<<<dim3(Kk / 64, Qq / 64, Bb), 256, sc_smem>>>(w_v, valid_lens);

    softmax_kernel<<<Bb * Qq, 256>>>(valid_lens);

    av_kernel<<<dim3(VDd / 64, Qq / 64, Bb), 512>>>(values, valid_lens, out);
}